// round 2
// baseline (speedup 1.0000x reference)
#include <cuda_runtime.h>

// Problem constants (fixed by the reference: B=4, H=16, S=2048, D=64)
#define S_LEN 2048
#define DH    64
#define BHN   64            // B*H
#define BQ    128           // query rows per block
#define BKT   64            // key rows per tile

// smem layout (floats). Even pitches so 8-byte (float2/ull) accesses stay aligned.
#define PT    130
#define QT_OFF 0                       // Qt[d][r]      : 64 x PT (transposed Q)
#define KS_OFF (QT_OFF + 64 * PT)      // Ksd[kr][2d]   : 64 x PT (K duplicated)
#define VS_OFF (KS_OFF + 64 * PT)      // Vsd[j][2c]    : 64 x PT (V duplicated)
#define ET_OFF (VS_OFF + 64 * PT)      // Et[kc][r]     : 64 x PT (transposed E)
#define LS_OFF (ET_OFF + 64 * PT)      // Ls[r]         : 128
#define SM_FLOATS (LS_OFF + BQ)

typedef unsigned long long ull;

// packed f32x2 FMA: d = a * b + d   (SASS FFMA2 — 2 lane-FMAs per fma-pipe slot)
__device__ __forceinline__ void fma2(ull& d, ull a, ull b) {
    asm("fma.rn.f32x2 %0, %1, %2, %0;" : "+l"(d) : "l"(a), "l"(b));
}
__device__ __forceinline__ void upk(ull p, float& lo, float& hi) {
    asm("mov.b64 {%0, %1}, %2;" : "=f"(lo), "=f"(hi) : "l"(p));
}

// per-row 1/sum(exp) scratch
__device__ float g_inv[(size_t)BHN * S_LEN];

__global__ __launch_bounds__(256, 1) void attn_pass1(
    const float* __restrict__ q, const float* __restrict__ k,
    const float* __restrict__ v, const int* __restrict__ mask,
    float* __restrict__ out, float* __restrict__ p)
{
    extern __shared__ float sm[];

    const int tid = threadIdx.x;
    const int tx = tid & 15;           // 16 thread-cols (4 key/val cols each)
    const int ty = tid >> 4;           // 16 thread-rows (8 query rows each)
    const int tx4 = tx * 4, ty8 = ty * 8;
    const int bh = blockIdx.y;
    const int q0 = blockIdx.x * BQ;

    // ---- load Q tile [BQ x DH] transposed into Qt[d][r]
    const float* qg = q + ((size_t)bh * S_LEN + q0) * DH;
    for (int i = tid; i < BQ * DH / 4; i += 256) {
        float4 t = ((const float4*)qg)[i];
        int r = (i * 4) / DH, d = (i * 4) % DH;
        sm[QT_OFF + (d + 0) * PT + r] = t.x;
        sm[QT_OFF + (d + 1) * PT + r] = t.y;
        sm[QT_OFF + (d + 2) * PT + r] = t.z;
        sm[QT_OFF + (d + 3) * PT + r] = t.w;
    }

    ull oacc2[4][4];                   // row-pairs (2u,2u+1) x 4 cols
    #pragma unroll
    for (int u = 0; u < 4; ++u)
        #pragma unroll
        for (int c = 0; c < 4; ++c) oacc2[u][c] = 0ULL;
    float lsum[8];
    #pragma unroll
    for (int i = 0; i < 8; ++i) lsum[i] = 0.f;

    const float scale = 0.125f;        // 1/sqrt(64)

    for (int kb = 0; kb < S_LEN / BKT; ++kb) {
        __syncthreads();               // prev tile's GEMM2 done before overwrite
        // ---- load K,V tiles [BKT x DH], value-duplicated for packed b-operand
        const float* kg = k + ((size_t)bh * S_LEN + kb * BKT) * DH;
        const float* vg = v + ((size_t)bh * S_LEN + kb * BKT) * DH;
        for (int i = tid; i < BKT * DH / 4; i += 256) {
            int r = (i * 4) / DH, d = (i * 4) % DH;
            float4 t = ((const float4*)kg)[i];
            float2* dk = (float2*)&sm[KS_OFF + r * PT + 2 * d];
            dk[0] = make_float2(t.x, t.x); dk[1] = make_float2(t.y, t.y);
            dk[2] = make_float2(t.z, t.z); dk[3] = make_float2(t.w, t.w);
            float4 u = ((const float4*)vg)[i];
            float2* dv = (float2*)&sm[VS_OFF + r * PT + 2 * d];
            dv[0] = make_float2(u.x, u.x); dv[1] = make_float2(u.y, u.y);
            dv[2] = make_float2(u.z, u.z); dv[3] = make_float2(u.w, u.w);
        }
        __syncthreads();

        // ---- GEMM1 (packed): S row-pairs x 4 cols over d
        ull acc2[4][4];
        #pragma unroll
        for (int u = 0; u < 4; ++u)
            #pragma unroll
            for (int c = 0; c < 4; ++c) acc2[u][c] = 0ULL;

        #pragma unroll 8
        for (int d = 0; d < DH; ++d) {
            ull a2[4], b2[4];
            #pragma unroll
            for (int u = 0; u < 4; ++u)
                a2[u] = *(const ull*)&sm[QT_OFF + d * PT + ty8 + 2 * u];
            #pragma unroll
            for (int c = 0; c < 4; ++c)
                b2[c] = *(const ull*)&sm[KS_OFF + (tx4 + c) * PT + 2 * d];
            #pragma unroll
            for (int u = 0; u < 4; ++u)
                #pragma unroll
                for (int c = 0; c < 4; ++c) fma2(acc2[u][c], a2[u], b2[c]);
        }

        // ---- mask + exp; write e to gmem p (unnormalized) and Et (transposed)
        const int kc = kb * BKT + tx4;
        #pragma unroll
        for (int i = 0; i < 8; ++i) {
            const int u = i >> 1, h = i & 1;
            const int qr = q0 + ty8 + i;
            float x[4];
            #pragma unroll
            for (int c = 0; c < 4; ++c) {
                float lo, hi; upk(acc2[u][c], lo, hi);
                x[c] = h ? hi : lo;
            }
            const int4 m = *(const int4*)(mask + (size_t)qr * S_LEN + kc);
            float4 e;
            e.x = m.x ? __expf(x[0] * scale) : 0.f;
            e.y = m.y ? __expf(x[1] * scale) : 0.f;
            e.z = m.z ? __expf(x[2] * scale) : 0.f;
            e.w = m.w ? __expf(x[3] * scale) : 0.f;
            *(float4*)(p + ((size_t)bh * S_LEN + qr) * S_LEN + kc) = e;
            sm[ET_OFF + (tx4 + 0) * PT + ty8 + i] = e.x;
            sm[ET_OFF + (tx4 + 1) * PT + ty8 + i] = e.y;
            sm[ET_OFF + (tx4 + 2) * PT + ty8 + i] = e.z;
            sm[ET_OFF + (tx4 + 3) * PT + ty8 + i] = e.w;

            float part = (e.x + e.y) + (e.z + e.w);
            part += __shfl_down_sync(0xffffffffu, part, 8, 16);
            part += __shfl_down_sync(0xffffffffu, part, 4, 16);
            part += __shfl_down_sync(0xffffffffu, part, 2, 16);
            part += __shfl_down_sync(0xffffffffu, part, 1, 16);
            if (tx == 0) lsum[i] += part;
        }
        __syncthreads();               // Et visible

        // ---- GEMM2 (packed): O row-pairs x 4 cols over j
        #pragma unroll 8
        for (int j = 0; j < BKT; ++j) {
            ull a2[4], b2[4];
            #pragma unroll
            for (int u = 0; u < 4; ++u)
                a2[u] = *(const ull*)&sm[ET_OFF + j * PT + ty8 + 2 * u];
            #pragma unroll
            for (int c = 0; c < 4; ++c)
                b2[c] = *(const ull*)&sm[VS_OFF + j * PT + 2 * (tx4 + c)];
            #pragma unroll
            for (int u = 0; u < 4; ++u)
                #pragma unroll
                for (int c = 0; c < 4; ++c) fma2(oacc2[u][c], a2[u], b2[c]);
        }
    }

    // ---- finalize: 1/l, publish for scale kernel, normalize out
    if (tx == 0) {
        #pragma unroll
        for (int i = 0; i < 8; ++i) {
            float inv = 1.f / lsum[i];
            sm[LS_OFF + ty8 + i] = inv;
            g_inv[(size_t)bh * S_LEN + q0 + ty8 + i] = inv;
        }
    }
    __syncthreads();
    #pragma unroll
    for (int i = 0; i < 8; ++i) {
        const int u = i >> 1, h = i & 1;
        float inv = sm[LS_OFF + ty8 + i];
        float4 o;
        #pragma unroll
        for (int c = 0; c < 4; ++c) {
            float lo, hi; upk(oacc2[u][c], lo, hi);
            ((float*)&o)[c] = (h ? hi : lo) * inv;
        }
        *(float4*)(out + ((size_t)bh * S_LEN + q0 + ty8 + i) * DH + tx4) = o;
    }
}

// In-place normalization of p_attn: p[row, :] *= 1/l[row]  (HBM-bound, done)
__global__ void scale_p(float* __restrict__ p)
{
    size_t i4 = (size_t)blockIdx.x * blockDim.x + threadIdx.x;  // float4 index
    float inv = g_inv[i4 >> 9];       // (i4*4)/2048
    float4* p4 = (float4*)p;
    float4 t = p4[i4];
    t.x *= inv; t.y *= inv; t.z *= inv; t.w *= inv;
    p4[i4] = t;
}

extern "C" void kernel_launch(void* const* d_in, const int* in_sizes, int n_in,
                              void* d_out, int out_size)
{
    const float* q    = (const float*)d_in[0];
    const float* k    = (const float*)d_in[1];
    const float* v    = (const float*)d_in[2];
    const int*   mask = (const int*)d_in[3];

    float* out = (float*)d_out;
    float* p   = out + (size_t)BHN * S_LEN * DH;   // out first, then p_attn

    const int smem_bytes = SM_FLOATS * 4;
    cudaFuncSetAttribute(attn_pass1, cudaFuncAttributeMaxDynamicSharedMemorySize,
                         smem_bytes);

    dim3 g1(S_LEN / BQ, BHN);
    attn_pass1<<<g1, 256, smem_bytes>>>(q, k, v, mask, out, p);

    size_t n4 = (size_t)BHN * S_LEN * S_LEN / 4;
    scale_p<<<(unsigned)(n4 / 256), 256>>>(p);
}

// round 5
// speedup vs baseline: 3.2662x; 3.2662x over previous
#include <cuda_runtime.h>
#include <cuda_bf16.h>
#include <cstdint>

// Problem constants: B=4, H=16, S=2048, D=64
#define S_LEN 2048
#define DH    64
#define BHN   64
#define BQ    128           // query rows per CTA
#define BKT   128           // key rows per tile
#define NTILE 16

// smem byte offsets: six [128 x 64] bf16 tiles (128B rows, xor-swizzled)
#define OFF_QH 0
#define OFF_QL 16384
#define OFF_KH 32768
#define OFF_KL 49152
#define OFF_VH 65536
#define OFF_VL 81920
#define SMEM_SZ 98304

typedef unsigned long long ull;

__device__ float g_inv[(size_t)BHN * S_LEN];

// ---------------- helpers ----------------
__device__ __forceinline__ uint32_t s2u(const void* p) {
    uint32_t a;
    asm("{ .reg .u64 t; cvta.to.shared.u64 t, %1; cvt.u32.u64 %0, t; }" : "=r"(a) : "l"(p));
    return a;
}
__device__ __forceinline__ void ldsm4(uint32_t a, uint32_t* r) {
    asm volatile("ldmatrix.sync.aligned.m8n8.x4.shared.b16 {%0,%1,%2,%3}, [%4];"
                 : "=r"(r[0]), "=r"(r[1]), "=r"(r[2]), "=r"(r[3]) : "r"(a));
}
__device__ __forceinline__ void ldsm4t(uint32_t a, uint32_t* r) {
    asm volatile("ldmatrix.sync.aligned.m8n8.x4.trans.shared.b16 {%0,%1,%2,%3}, [%4];"
                 : "=r"(r[0]), "=r"(r[1]), "=r"(r[2]), "=r"(r[3]) : "r"(a));
}
__device__ __forceinline__ void mma_bf16(float* d, const uint32_t* a,
                                         uint32_t b0, uint32_t b1) {
    asm volatile("mma.sync.aligned.m16n8k16.row.col.f32.bf16.bf16.f32 "
                 "{%0,%1,%2,%3},{%4,%5,%6,%7},{%8,%9},{%0,%1,%2,%3};"
                 : "+f"(d[0]), "+f"(d[1]), "+f"(d[2]), "+f"(d[3])
                 : "r"(a[0]), "r"(a[1]), "r"(a[2]), "r"(a[3]), "r"(b0), "r"(b1));
}
// pack two f32 -> bf16x2 (lo in low half / element 0)
__device__ __forceinline__ uint32_t pk2(float lo, float hi) {
    uint32_t r;
    asm("cvt.rn.bf16x2.f32 %0, %1, %2;" : "=r"(r) : "f"(hi), "f"(lo));
    return r;
}
__device__ __forceinline__ float lo16f(uint32_t u) { return __uint_as_float(u << 16); }
__device__ __forceinline__ float hi16f(uint32_t u) { return __uint_as_float(u & 0xFFFF0000u); }

// exp(0.125*x) on the FMA pipe: 2^(x*0.125*log2e) via magic-round + deg-5 poly
__device__ __forceinline__ float fexp8(float x) {
    float t  = x * 0.18033688011112042f;        // 0.125 * log2(e)
    float ft = t + 12582912.0f;                 // rint via magic
    float f  = t - (ft - 12582912.0f);          // f in [-0.5, 0.5]
    float pl = 0.0013333558f;
    pl = fmaf(pl, f, 0.0096181291f);
    pl = fmaf(pl, f, 0.0555041087f);
    pl = fmaf(pl, f, 0.2402265069f);
    pl = fmaf(pl, f, 0.6931471806f);
    pl = fmaf(pl, f, 1.0f);
    return __int_as_float(__float_as_int(pl) + (__float_as_int(ft) << 23));
}

// load a [128 x 64] fp32 tile, split to bf16 hi/lo, store swizzled (128B rows)
__device__ __forceinline__ void ldcvt(const float* __restrict__ g, char* smp,
                                      int hoff, int loff, int tid) {
    const float4* g4 = (const float4*)g;
    #pragma unroll
    for (int it = 0; it < 8; ++it) {
        int i = tid + it * 256;
        float4 t = g4[i];
        int row = i >> 4, d0 = (i & 15) << 2;
        uint32_t off = (uint32_t)row * 128 +
                       (((uint32_t)(d0 << 1)) ^ (((uint32_t)row & 7) << 4));
        uint32_t h01 = pk2(t.x, t.y), h23 = pk2(t.z, t.w);
        uint32_t l01 = pk2(t.x - lo16f(h01), t.y - hi16f(h01));
        uint32_t l23 = pk2(t.z - lo16f(h23), t.w - hi16f(h23));
        *(ull*)(smp + hoff + off) = (ull)h01 | ((ull)h23 << 32);
        *(ull*)(smp + loff + off) = (ull)l01 | ((ull)l23 << 32);
    }
}

__global__ __launch_bounds__(256, 1)
void attn_mma(const float* __restrict__ q, const float* __restrict__ k,
              const float* __restrict__ v, const int* __restrict__ mask,
              float* __restrict__ out, float* __restrict__ p)
{
    extern __shared__ char sm[];
    const uint32_t sb = s2u(sm);
    const int tid = threadIdx.x;
    const int wid = tid >> 5, lane = tid & 31;
    const int bh = blockIdx.y;
    const int q0 = blockIdx.x * BQ;
    const int mr = wid * 16;                   // this warp's 16 query rows

    // Q tile once
    ldcvt(q + ((size_t)bh * S_LEN + q0) * DH, sm, OFF_QH, OFF_QL, tid);

    float Oacc[8][4];
    #pragma unroll
    for (int i = 0; i < 8; ++i)
        #pragma unroll
        for (int c = 0; c < 4; ++c) Oacc[i][c] = 0.f;
    float esum0 = 0.f, esum1 = 0.f;

    // epilogue thread mapping (m16n8 accum layout)
    const int r0l = mr + (lane >> 2);          // local row (and r0l+8)
    const int coff = (lane & 3) * 2;

    // ldmatrix lane->row/col mapping (XOR applied per-access AFTER col adds)
    // A (Q/E rows)
    const int arow = mr + (lane & 15);
    const uint32_t arowoff = (uint32_t)arow * 128;
    const uint32_t acol0 = ((uint32_t)(lane >> 4)) << 4;
    const uint32_t axor = ((uint32_t)arow & 7) << 4;
    // B (K rows)
    const int nrow = ((lane >> 4) << 3) + (lane & 7);
    const uint32_t nrowoff = (uint32_t)nrow * 128;
    const uint32_t ncol0 = (((uint32_t)lane >> 3) & 1) << 4;
    const uint32_t nxor = ((uint32_t)nrow & 7) << 4;
    // V trans (V rows)
    const int vrow = (((lane >> 3) & 1) << 3) + (lane & 7);
    const uint32_t vrowoff = (uint32_t)vrow * 128;
    const uint32_t vcol0 = ((uint32_t)(lane >> 4)) << 4;
    const uint32_t vxor = ((uint32_t)vrow & 7) << 4;

    for (int kb = 0; kb < NTILE; ++kb) {
        __syncthreads();                       // prev tile's MMAs done before overwrite
        ldcvt(k + ((size_t)bh * S_LEN + kb * BKT) * DH, sm, OFF_KH, OFF_KL, tid);
        ldcvt(v + ((size_t)bh * S_LEN + kb * BKT) * DH, sm, OFF_VH, OFF_VL, tid);
        __syncthreads();

        // ---- GEMM1: S[16 x 128] per warp = Q . K^T (3-term bf16 split)
        float acc[16][4];
        #pragma unroll
        for (int i = 0; i < 16; ++i)
            #pragma unroll
            for (int c = 0; c < 4; ++c) acc[i][c] = 0.f;

        #pragma unroll
        for (int ks = 0; ks < 4; ++ks) {
            uint32_t ah[4], al[4];
            const uint32_t ao = arowoff + ((acol0 + (uint32_t)ks * 32) ^ axor);
            ldsm4(sb + OFF_QH + ao, ah);
            ldsm4(sb + OFF_QL + ao, al);
            #pragma unroll
            for (int np = 0; np < 8; ++np) {
                uint32_t bh4[4], bl4[4];
                const uint32_t bo = nrowoff + (uint32_t)np * 2048 +
                                    ((ncol0 + (uint32_t)ks * 32) ^ nxor);
                ldsm4(sb + OFF_KH + bo, bh4);
                ldsm4(sb + OFF_KL + bo, bl4);
                mma_bf16(acc[np * 2], ah, bh4[0], bh4[1]);
                mma_bf16(acc[np * 2], ah, bl4[0], bl4[1]);
                mma_bf16(acc[np * 2], al, bh4[0], bh4[1]);
                mma_bf16(acc[np * 2 + 1], ah, bh4[2], bh4[3]);
                mma_bf16(acc[np * 2 + 1], ah, bl4[2], bl4[3]);
                mma_bf16(acc[np * 2 + 1], al, bh4[2], bh4[3]);
            }
        }

        // ---- epilogue: mask + exp (FMA pipe), p write, pack E frags in regs
        uint32_t Eh[8][4], El[8][4];
        const int* mrow0 = mask + (size_t)(q0 + r0l) * S_LEN + kb * BKT + coff;
        const int* mrow1 = mrow0 + 8 * S_LEN;
        float* prow0 = p + ((size_t)(bh * S_LEN) + q0 + r0l) * S_LEN + kb * BKT + coff;
        float* prow1 = prow0 + (size_t)8 * S_LEN;
        #pragma unroll
        for (int nt = 0; nt < 16; ++nt) {
            const int2 m0 = *(const int2*)(mrow0 + nt * 8);
            const int2 m1 = *(const int2*)(mrow1 + nt * 8);
            float e0 = m0.x ? fexp8(acc[nt][0]) : 0.f;
            float e1 = m0.y ? fexp8(acc[nt][1]) : 0.f;
            float e2 = m1.x ? fexp8(acc[nt][2]) : 0.f;
            float e3 = m1.y ? fexp8(acc[nt][3]) : 0.f;
            *(float2*)(prow0 + nt * 8) = make_float2(e0, e1);
            *(float2*)(prow1 + nt * 8) = make_float2(e2, e3);
            esum0 += e0 + e1;
            esum1 += e2 + e3;
            uint32_t u01 = pk2(e0, e1), u23 = pk2(e2, e3);
            const int kk = nt >> 1, sl = (nt & 1) * 2;
            Eh[kk][sl + 0] = u01;
            Eh[kk][sl + 1] = u23;
            El[kk][sl + 0] = pk2(e0 - lo16f(u01), e1 - hi16f(u01));
            El[kk][sl + 1] = pk2(e2 - lo16f(u23), e3 - hi16f(u23));
        }

        // ---- GEMM2: O[16 x 64] += E . V (V via ldmatrix.trans, 3-term split)
        #pragma unroll
        for (int kk = 0; kk < 8; ++kk) {
            const uint32_t vrt = vrowoff + (uint32_t)kk * 2048;
            #pragma unroll
            for (int dt2 = 0; dt2 < 4; ++dt2) {
                uint32_t vh4[4], vl4[4];
                const uint32_t o = vrt + ((vcol0 + (uint32_t)dt2 * 32) ^ vxor);
                ldsm4t(sb + OFF_VH + o, vh4);
                ldsm4t(sb + OFF_VL + o, vl4);
                mma_bf16(Oacc[dt2 * 2], Eh[kk], vh4[0], vh4[1]);
                mma_bf16(Oacc[dt2 * 2], Eh[kk], vl4[0], vl4[1]);
                mma_bf16(Oacc[dt2 * 2], El[kk], vh4[0], vh4[1]);
                mma_bf16(Oacc[dt2 * 2 + 1], Eh[kk], vh4[2], vh4[3]);
                mma_bf16(Oacc[dt2 * 2 + 1], Eh[kk], vl4[2], vl4[3]);
                mma_bf16(Oacc[dt2 * 2 + 1], El[kk], vh4[2], vh4[3]);
            }
        }
    }

    // ---- row sums (quad reduce), publish 1/l, write normalized out
    esum0 += __shfl_xor_sync(0xffffffffu, esum0, 1);
    esum0 += __shfl_xor_sync(0xffffffffu, esum0, 2);
    esum1 += __shfl_xor_sync(0xffffffffu, esum1, 1);
    esum1 += __shfl_xor_sync(0xffffffffu, esum1, 2);
    const float inv0 = 1.f / esum0, inv1 = 1.f / esum1;
    if ((lane & 3) == 0) {
        g_inv[(size_t)bh * S_LEN + q0 + r0l] = inv0;
        g_inv[(size_t)bh * S_LEN + q0 + r0l + 8] = inv1;
    }
    float* orow0 = out + ((size_t)(bh * S_LEN) + q0 + r0l) * DH + coff;
    float* orow1 = orow0 + 8 * DH;
    #pragma unroll
    for (int dt = 0; dt < 8; ++dt) {
        *(float2*)(orow0 + dt * 8) = make_float2(Oacc[dt][0] * inv0, Oacc[dt][1] * inv0);
        *(float2*)(orow1 + dt * 8) = make_float2(Oacc[dt][2] * inv1, Oacc[dt][3] * inv1);
    }
}

// In-place normalization of p_attn (HBM-bound, at roofline)
__global__ void scale_p(float* __restrict__ p)
{
    size_t i4 = (size_t)blockIdx.x * blockDim.x + threadIdx.x;
    float inv = g_inv[i4 >> 9];
    float4* p4 = (float4*)p;
    float4 t = p4[i4];
    t.x *= inv; t.y *= inv; t.z *= inv; t.w *= inv;
    p4[i4] = t;
}

extern "C" void kernel_launch(void* const* d_in, const int* in_sizes, int n_in,
                              void* d_out, int out_size)
{
    const float* q    = (const float*)d_in[0];
    const float* k    = (const float*)d_in[1];
    const float* v    = (const float*)d_in[2];
    const int*   mask = (const int*)d_in[3];

    float* out = (float*)d_out;
    float* p   = out + (size_t)BHN * S_LEN * DH;

    cudaFuncSetAttribute(attn_mma, cudaFuncAttributeMaxDynamicSharedMemorySize, SMEM_SZ);
    dim3 g1(S_LEN / BQ, BHN);
    attn_mma<<<g1, 256, SMEM_SZ>>>(q, k, v, mask, out, p);

    size_t n4 = (size_t)BHN * S_LEN * S_LEN / 4;
    scale_p<<<(unsigned)(n4 / 256), 256>>>(p);
}